// round 1
// baseline (speedup 1.0000x reference)
#include <cuda_runtime.h>
#include <cuda_bf16.h>

#define NS 2048
#define CC 512
#define HW 49
#define EPS 1e-5f
#define ELEMS (CC * HW)            // 25088 floats per sample
#define SMEM_BYTES (ELEMS * 4)     // 100352 bytes
#define VEC4 (ELEMS / 4)           // 6272

__global__ __launch_bounds__(512, 2)
void gate_fused_kernel(const float* __restrict__ x, float* __restrict__ out) {
    extern __shared__ float s[];               // [ELEMS] sample tile
    __shared__ float warp_y[16];
    __shared__ float warp_y2[16];
    __shared__ float s_mean, s_inv;

    const int n   = blockIdx.x;
    const int tid = threadIdx.x;

    const float4* __restrict__ x4 = (const float4*)(x + (size_t)n * ELEMS);
    float4* __restrict__ o4       = (float4*)(out + (size_t)n * ELEMS);
    float4* s4 = (float4*)s;

    // 1) coalesced gmem -> smem
    #pragma unroll 4
    for (int i = tid; i < VEC4; i += 512) s4[i] = x4[i];
    __syncthreads();

    // 2) per-channel spatial mean (thread c owns channel c; stride-49 words is conflict-free)
    float* row = s + tid * HW;
    float acc = 0.0f;
    #pragma unroll
    for (int i = 0; i < HW; i++) acc += row[i];
    const float y = acc * (1.0f / (float)HW);

    // 3) block reduction of sum(y), sum(y*y) over C=512
    float sy = y, sy2 = y * y;
    #pragma unroll
    for (int o = 16; o > 0; o >>= 1) {
        sy  += __shfl_xor_sync(0xffffffffu, sy,  o);
        sy2 += __shfl_xor_sync(0xffffffffu, sy2, o);
    }
    const int wid = tid >> 5, lid = tid & 31;
    if (lid == 0) { warp_y[wid] = sy; warp_y2[wid] = sy2; }
    __syncthreads();
    if (wid == 0) {
        float a = (lid < 16) ? warp_y[lid]  : 0.0f;
        float b = (lid < 16) ? warp_y2[lid] : 0.0f;
        #pragma unroll
        for (int o = 8; o > 0; o >>= 1) {
            a += __shfl_xor_sync(0xffffffffu, a, o);
            b += __shfl_xor_sync(0xffffffffu, b, o);
        }
        if (lid == 0) {
            const float m   = a * (1.0f / (float)CC);
            const float mx2 = b * (1.0f / (float)CC);
            float var = mx2 - m * m;
            var = var > 0.0f ? var : 0.0f;
            s_mean = m;
            s_inv  = rsqrtf(var + EPS);
        }
    }
    __syncthreads();

    // 4) gate and in-place scale of this thread's channel row
    {
        const float yn   = (y - s_mean) * s_inv;
        const float gate = __expf(-yn * yn);      // exp(-0.5 * 2.0 * yn^2)
        #pragma unroll
        for (int i = 0; i < HW; i++) row[i] *= gate;
    }
    __syncthreads();

    // 5) coalesced smem -> gmem
    #pragma unroll 4
    for (int i = tid; i < VEC4; i += 512) o4[i] = s4[i];
}

extern "C" void kernel_launch(void* const* d_in, const int* in_sizes, int n_in,
                              void* d_out, int out_size) {
    (void)in_sizes; (void)n_in; (void)out_size;
    const float* x = (const float*)d_in[0];
    float* out = (float*)d_out;
    cudaFuncSetAttribute(gate_fused_kernel,
                         cudaFuncAttributeMaxDynamicSharedMemorySize, SMEM_BYTES);
    gate_fused_kernel<<<NS, 512, SMEM_BYTES>>>(x, out);
}

// round 5
// speedup vs baseline: 1.0722x; 1.0722x over previous
#include <cuda_runtime.h>
#include <cuda_bf16.h>

#define NS 2048
#define CC 512
#define HW 49
#define EPS 1e-5f
#define ELEMS (CC * HW)            // 25088 floats per sample
#define VEC4 (ELEMS / 4)           // 6272

__global__ __launch_bounds__(512, 4)
void gate_twopass_kernel(const float* __restrict__ x, float* __restrict__ out) {
    __shared__ float y_s[CC];          // per-channel spatial means
    __shared__ float gate_s[CC];       // per-channel gates
    __shared__ float warp_a[16];
    __shared__ float warp_b[16];
    __shared__ float s_mean, s_inv;

    const int n   = blockIdx.x;
    const int tid = threadIdx.x;
    const int wid = tid >> 5;
    const int lid = tid & 31;

    const float* __restrict__ xs = x + (size_t)n * ELEMS;
    float*       __restrict__ os = out + (size_t)n * ELEMS;

    // ---- Pass 1: per-channel spatial mean, one warp per channel ----
    // warp wid handles channels c = k*16 + wid; lanes read 49 contiguous floats.
    #pragma unroll 4
    for (int k = 0; k < CC / 16; k++) {
        const int c = k * 16 + wid;
        const float* __restrict__ row = xs + c * HW;
        float v = row[lid];
        if (lid < HW - 32) v += row[32 + lid];
        #pragma unroll
        for (int o = 16; o > 0; o >>= 1)
            v += __shfl_xor_sync(0xffffffffu, v, o);
        if (lid == 0) y_s[c] = v * (1.0f / (float)HW);
    }
    __syncthreads();

    // ---- Stats over y[512] + gate computation ----
    const float y = y_s[tid];
    float sy = y, sy2 = y * y;
    #pragma unroll
    for (int o = 16; o > 0; o >>= 1) {
        sy  += __shfl_xor_sync(0xffffffffu, sy,  o);
        sy2 += __shfl_xor_sync(0xffffffffu, sy2, o);
    }
    if (lid == 0) { warp_a[wid] = sy; warp_b[wid] = sy2; }
    __syncthreads();
    if (wid == 0) {
        float a = (lid < 16) ? warp_a[lid] : 0.0f;
        float b = (lid < 16) ? warp_b[lid] : 0.0f;
        #pragma unroll
        for (int o = 8; o > 0; o >>= 1) {
            a += __shfl_xor_sync(0xffffffffu, a, o);
            b += __shfl_xor_sync(0xffffffffu, b, o);
        }
        if (lid == 0) {
            const float m   = a * (1.0f / (float)CC);
            const float mx2 = b * (1.0f / (float)CC);
            float var = mx2 - m * m;
            var = var > 0.0f ? var : 0.0f;
            s_mean = m;
            s_inv  = rsqrtf(var + EPS);
        }
    }
    __syncthreads();
    {
        const float yn = (y - s_mean) * s_inv;
        gate_s[tid] = __expf(-yn * yn);   // exp(-0.5 * C_PARAM * yn^2), C_PARAM = 2
    }
    __syncthreads();

    // ---- Pass 2: re-read x (L2-resident), apply gate, streaming store ----
    const float4* __restrict__ x4 = (const float4*)xs;
    float4*       __restrict__ o4 = (float4*)os;
    #pragma unroll 2
    for (int i = tid; i < VEC4; i += 512) {
        float4 v = __ldcs(x4 + i);
        const unsigned e  = 4u * (unsigned)i;
        const unsigned c0 = e / 49u;            // magic-mul division
        const unsigned c1 = (e + 1u) / 49u;
        const unsigned c2 = (e + 2u) / 49u;
        const unsigned c3 = (e + 3u) / 49u;
        v.x *= gate_s[c0];
        v.y *= gate_s[c1];
        v.z *= gate_s[c2];
        v.w *= gate_s[c3];
        __stcs(o4 + i, v);
    }
}

extern "C" void kernel_launch(void* const* d_in, const int* in_sizes, int n_in,
                              void* d_out, int out_size) {
    (void)in_sizes; (void)n_in; (void)out_size;
    const float* x = (const float*)d_in[0];
    float* out = (float*)d_out;
    gate_twopass_kernel<<<NS, 512>>>(x, out);
}

// round 7
// speedup vs baseline: 1.3882x; 1.2947x over previous
#include <cuda_runtime.h>
#include <cuda_bf16.h>

#define NS 2048
#define CC 512
#define HW 49
#define EPS 1e-5f
#define ELEMS (CC * HW)            // 25088 floats per sample
#define VEC4 (ELEMS / 4)           // 6272 = 512*12 + 128

__global__ __launch_bounds__(512, 3)
void gate_twopass_kernel(const float* __restrict__ x, float* __restrict__ out) {
    __shared__ float y_s[CC];          // per-channel spatial means
    __shared__ float gate_s[CC + 4];   // padded: c+1 probe at c=511 stays in-bounds
    __shared__ float warp_a[16];
    __shared__ float warp_b[16];
    __shared__ float s_mean, s_inv;

    const int n   = blockIdx.x;
    const int tid = threadIdx.x;
    const int wid = tid >> 5;
    const int lid = tid & 31;

    const float* __restrict__ xs = x + (size_t)n * ELEMS;
    float*       __restrict__ os = out + (size_t)n * ELEMS;

    // ---- Pass 1: per-channel spatial mean, one warp per channel ----
    #pragma unroll 4
    for (int k = 0; k < CC / 16; k++) {
        const int c = k * 16 + wid;
        const float* __restrict__ row = xs + c * HW;
        float v = row[lid];
        if (lid < HW - 32) v += row[32 + lid];
        #pragma unroll
        for (int o = 16; o > 0; o >>= 1)
            v += __shfl_xor_sync(0xffffffffu, v, o);
        if (lid == 0) y_s[c] = v * (1.0f / (float)HW);
    }
    __syncthreads();

    // ---- Stats over y[512] + per-channel gate ----
    const float y = y_s[tid];
    float sy = y, sy2 = y * y;
    #pragma unroll
    for (int o = 16; o > 0; o >>= 1) {
        sy  += __shfl_xor_sync(0xffffffffu, sy,  o);
        sy2 += __shfl_xor_sync(0xffffffffu, sy2, o);
    }
    if (lid == 0) { warp_a[wid] = sy; warp_b[wid] = sy2; }
    __syncthreads();
    if (wid == 0) {
        float a = (lid < 16) ? warp_a[lid] : 0.0f;
        float b = (lid < 16) ? warp_b[lid] : 0.0f;
        #pragma unroll
        for (int o = 8; o > 0; o >>= 1) {
            a += __shfl_xor_sync(0xffffffffu, a, o);
            b += __shfl_xor_sync(0xffffffffu, b, o);
        }
        if (lid == 0) {
            const float m   = a * (1.0f / (float)CC);
            const float mx2 = b * (1.0f / (float)CC);
            float var = mx2 - m * m;
            var = var > 0.0f ? var : 0.0f;
            s_mean = m;
            s_inv  = rsqrtf(var + EPS);
        }
    }
    __syncthreads();
    {
        const float yn = (y - s_mean) * s_inv;
        gate_s[tid] = __expf(-yn * yn);   // exp(-0.5 * C_PARAM * yn^2), C_PARAM = 2
    }
    __syncthreads();

    // ---- Pass 2: re-read x (L2-resident), gate, streaming store ----
    // Incremental channel tracking: e advances by 2048 = 41*49 + 39 per iter.
    const float4* __restrict__ x4 = (const float4*)xs;
    float4*       __restrict__ o4 = (float4*)os;

    unsigned i = (unsigned)tid;
    unsigned c = ((unsigned)tid * 4u) / 49u;
    unsigned r = (unsigned)tid * 4u - c * 49u;     // remainder in [0,48]

    #pragma unroll 4
    for (int k = 0; k < 12; k++) {
        float4 v = __ldcs(x4 + i);
        const float g0 = gate_s[c];
        const float g1 = gate_s[c + 1];
        v.x *= g0;                                 // r < 49 always
        v.y *= (r + 1u < 49u) ? g0 : g1;
        v.z *= (r + 2u < 49u) ? g0 : g1;
        v.w *= (r + 3u < 49u) ? g0 : g1;
        __stcs(o4 + i, v);
        i += 512u;
        c += 41u; r += 39u;
        if (r >= 49u) { r -= 49u; c += 1u; }
    }
    // tail: first 128 threads handle float4s 6144..6271
    if (tid < 128) {
        const unsigned ii = (unsigned)tid + 6144u;
        const unsigned e  = ii * 4u;
        const unsigned ct = e / 49u;
        const unsigned rt = e - ct * 49u;
        float4 v = __ldcs(x4 + ii);
        const float g0 = gate_s[ct];
        const float g1 = gate_s[ct + 1];
        v.x *= g0;
        v.y *= (rt + 1u < 49u) ? g0 : g1;
        v.z *= (rt + 2u < 49u) ? g0 : g1;
        v.w *= (rt + 3u < 49u) ? g0 : g1;
        __stcs(o4 + ii, v);
    }
}

extern "C" void kernel_launch(void* const* d_in, const int* in_sizes, int n_in,
                              void* d_out, int out_size) {
    (void)in_sizes; (void)n_in; (void)out_size;
    const float* x = (const float*)d_in[0];
    float* out = (float*)d_out;
    gate_twopass_kernel<<<NS, 512>>>(x, out);
}

// round 8
// speedup vs baseline: 1.3909x; 1.0019x over previous
#include <cuda_runtime.h>
#include <cuda_bf16.h>

#define NS 2048
#define CC 512
#define HW 49
#define EPS 1e-5f
#define ELEMS (CC * HW)            // 25088 floats per sample
#define VEC4 (ELEMS / 4)           // 6272 = 512*12 + 128

__global__ __launch_bounds__(512, 4)
void gate_twopass_kernel(const float* __restrict__ x, float* __restrict__ out) {
    __shared__ float y_s[CC];          // per-channel spatial means
    __shared__ float gate_s[CC + 4];   // padded: c+1 probe at c=511 stays in-bounds
    __shared__ float warp_a[16];
    __shared__ float warp_b[16];
    __shared__ float s_mean, s_inv;

    const int n   = blockIdx.x;
    const int tid = threadIdx.x;
    const int wid = tid >> 5;
    const int lid = tid & 31;

    const float* __restrict__ xs = x + (size_t)n * ELEMS;
    float*       __restrict__ os = out + (size_t)n * ELEMS;

    // ---- Pass 1: per-channel spatial mean, one warp per channel ----
    #pragma unroll 4
    for (int k = 0; k < CC / 16; k++) {
        const int c = k * 16 + wid;
        const float* __restrict__ row = xs + c * HW;
        float v = row[lid];
        if (lid < HW - 32) v += row[32 + lid];
        #pragma unroll
        for (int o = 16; o > 0; o >>= 1)
            v += __shfl_xor_sync(0xffffffffu, v, o);
        if (lid == 0) y_s[c] = v * (1.0f / (float)HW);
    }
    __syncthreads();

    // ---- Stats over y[512] + per-channel gate ----
    const float y = y_s[tid];
    float sy = y, sy2 = y * y;
    #pragma unroll
    for (int o = 16; o > 0; o >>= 1) {
        sy  += __shfl_xor_sync(0xffffffffu, sy,  o);
        sy2 += __shfl_xor_sync(0xffffffffu, sy2, o);
    }
    if (lid == 0) { warp_a[wid] = sy; warp_b[wid] = sy2; }
    __syncthreads();
    if (wid == 0) {
        float a = (lid < 16) ? warp_a[lid] : 0.0f;
        float b = (lid < 16) ? warp_b[lid] : 0.0f;
        #pragma unroll
        for (int o = 8; o > 0; o >>= 1) {
            a += __shfl_xor_sync(0xffffffffu, a, o);
            b += __shfl_xor_sync(0xffffffffu, b, o);
        }
        if (lid == 0) {
            const float m   = a * (1.0f / (float)CC);
            const float mx2 = b * (1.0f / (float)CC);
            float var = mx2 - m * m;
            var = var > 0.0f ? var : 0.0f;
            s_mean = m;
            s_inv  = rsqrtf(var + EPS);
        }
    }
    __syncthreads();
    {
        const float yn = (y - s_mean) * s_inv;
        gate_s[tid] = __expf(-yn * yn);   // exp(-0.5 * C_PARAM * yn^2), C_PARAM = 2
    }
    __syncthreads();

    // ---- Pass 2: re-read x (L2-resident), gate, streaming store ----
    // Incremental channel tracking: e advances by 2048 = 41*49 + 39 per iter.
    const float4* __restrict__ x4 = (const float4*)xs;
    float4*       __restrict__ o4 = (float4*)os;

    unsigned i = (unsigned)tid;
    unsigned c = ((unsigned)tid * 4u) / 49u;
    unsigned r = (unsigned)tid * 4u - c * 49u;     // remainder in [0,48]

    #pragma unroll 4
    for (int k = 0; k < 12; k++) {
        float4 v = __ldcs(x4 + i);
        const float g0 = gate_s[c];
        const float g1 = gate_s[c + 1];
        v.x *= g0;                                 // r < 49 always
        v.y *= (r + 1u < 49u) ? g0 : g1;
        v.z *= (r + 2u < 49u) ? g0 : g1;
        v.w *= (r + 3u < 49u) ? g0 : g1;
        __stcs(o4 + i, v);
        i += 512u;
        c += 41u; r += 39u;
        if (r >= 49u) { r -= 49u; c += 1u; }
    }
    // tail: first 128 threads handle float4s 6144..6271
    if (tid < 128) {
        const unsigned ii = (unsigned)tid + 6144u;
        const unsigned e  = ii * 4u;
        const unsigned ct = e / 49u;
        const unsigned rt = e - ct * 49u;
        float4 v = __ldcs(x4 + ii);
        const float g0 = gate_s[ct];
        const float g1 = gate_s[ct + 1];
        v.x *= g0;
        v.y *= (rt + 1u < 49u) ? g0 : g1;
        v.z *= (rt + 2u < 49u) ? g0 : g1;
        v.w *= (rt + 3u < 49u) ? g0 : g1;
        __stcs(o4 + ii, v);
    }
}

extern "C" void kernel_launch(void* const* d_in, const int* in_sizes, int n_in,
                              void* d_out, int out_size) {
    (void)in_sizes; (void)n_in; (void)out_size;
    const float* x = (const float*)d_in[0];
    float* out = (float*)d_out;
    gate_twopass_kernel<<<NS, 512>>>(x, out);
}